// round 12
// baseline (speedup 1.0000x reference)
#include <cuda_runtime.h>
#include <cstdint>
#include <math.h>

#define NHID   1024
#define LSTEPS 1024
#define TPBC   512          // cold kernel: 16 warps per CTA, one CTA per row
#define NPTC   2            // cold: neurons per thread
#define TPBF   128          // fix kernel
#define NPTF   8
#define NPRF   4
#define BMAX   4096

typedef unsigned long long u64;

__device__ int g_spiked[BMAX];   // per-row "any RF spike ever" flag

// ---- packed f32x2 ops (sm_100+) ----
__device__ __forceinline__ float2 ffma2(float2 a, float2 b, float2 c) {
    float2 d;
    asm("fma.rn.f32x2 %0, %1, %2, %3;"
        : "=l"(*(u64*)&d) : "l"(*(u64*)&a), "l"(*(u64*)&b), "l"(*(u64*)&c));
    return d;
}
__device__ __forceinline__ float2 fadd2(float2 a, float2 b) {
    float2 d;
    asm("add.rn.f32x2 %0, %1, %2;"
        : "=l"(*(u64*)&d) : "l"(*(u64*)&a), "l"(*(u64*)&b));
    return d;
}
__device__ __forceinline__ float2 fmul2(float2 a, float2 b) {
    float2 d;
    asm("mul.rn.f32x2 %0, %1, %2;"
        : "=l"(*(u64*)&d) : "l"(*(u64*)&a), "l"(*(u64*)&b));
    return d;
}

// Barrier + OR-reduction across the CTA in one BAR.RED instruction.
__device__ __forceinline__ bool bar_red_or(bool p) {
    unsigned r;
    asm volatile(
        "{\n\t"
        ".reg .pred pi, po;\n\t"
        "setp.ne.u32 pi, %1, 0;\n\t"
        "bar.red.or.pred po, 0, pi;\n\t"
        "selp.u32 %0, 1, 0, po;\n\t"
        "}"
        : "=r"(r) : "r"((unsigned)p) : "memory");
    return r != 0;
}

// ======================= COLD KERNEL (barrier-free mainloop) ==============
// While no RF spike has EVER occurred in a row, ref/ft/fts are exactly 0 and
// there is no recurrent coupling; alpha=beta=0 means an RF spike would not
// alter hy/hz. The uncoupled lif/hy/hzs trajectory is valid up to and
// including the first crossing; "did any neuron ever cross hy>1" (ref==0 =>
// spike cond (hy-1-ref)>0 <=> hy>1, Sterbenz-exact) decides everything.
// hzs = dt*hz:  hzs' = hzs*(1-dt*eps) + (-dt^2*gamma)*hy + k;  hy += hzs'.
// k = (lif>1) ? dt^2*sg : 0; reset: lif += k*(-1/(dt^2*sg)) == -spike (1 ulp).
// ONE f32x2 pair per thread (2 neurons): minimal per-warp dependency load,
// maximal scheduler slack. Per pair-step: 6 fma + 6 alu.
// x windows (8 steps) are staged in registers via 4x LDS.128 per iteration.
__global__ __launch_bounds__(TPBC, 3)
void coesn_cold(const float* __restrict__ x,      // (B, L)
                const float* __restrict__ x2h,    // (NHID)
                const float* __restrict__ bias,   // (NHID)
                const float* __restrict__ gamma_, // (NHID)
                const float* __restrict__ eps_,   // (NHID)
                const float* __restrict__ sgain,  // scalar
                float* __restrict__ out)          // (B, 2*NHID)
{
    __shared__ float xs2[2 * LSTEPS];   // duplicated: xs2[2t]=xs2[2t+1]=x[t]

    const int tid = threadIdx.x;
    const int b   = blockIdx.x;

    // Stage duplicated input: each thread expands one float2 (2 steps).
    {
        const float2 v = ((const float2*)(x + (size_t)b * LSTEPS))[tid];
        ((float4*)xs2)[tid] = make_float4(v.x, v.x, v.y, v.y);
    }

    const float dt = 0.01f;
    const float A  = 1.0f - dt / 20.0f;             // LIF decay
    const float kC = dt * dt * (*sgain);            // hzs kick per LIF spike
    const float2 A2  = make_float2(A, A);
    const float2 CR2 = make_float2(-1.0f / kC, -1.0f / kC);  // reset scale

    float2 W2, B2, EZ2, GN2;
    {
        float2 a;
        a = ((const float2*)x2h)[tid];
        W2 = make_float2(dt * a.x, dt * a.y);
        a = ((const float2*)bias)[tid];
        B2 = make_float2(dt * a.x, dt * a.y);
        a = ((const float2*)eps_)[tid];
        EZ2 = make_float2(1.f - dt * a.x, 1.f - dt * a.y);
        a = ((const float2*)gamma_)[tid];
        GN2 = make_float2(-dt * dt * a.x, -dt * dt * a.y);
    }

    float2 lif2 = make_float2(0.f, 0.f);
    float2 hy2  = make_float2(0.f, 0.f);
    float2 hzs2 = make_float2(0.f, 0.f);
    float2 mx2  = make_float2(-1.f, -1.f);   // running max of hy (both lanes)

    __syncthreads();   // xs2 ready

    const float4* xv = (const float4*)xs2;   // one float4 = 2 duplicated steps
    #pragma unroll 1
    for (int it = 0; it < LSTEPS / 8; ++it) {
        float4 q[4];
        #pragma unroll
        for (int i = 0; i < 4; ++i) q[i] = xv[it * 4 + i];   // 8 steps
        #pragma unroll
        for (int s = 0; s < 8; ++s) {
            const float* qf = (const float*)q;
            const float2 XT2 = make_float2(qf[2 * s], qf[2 * s + 1]);

            float2 I = ffma2(XT2, W2, B2);         // dt*(xt*w + b)
            lif2 = ffma2(lif2, A2, I);             // v = v*A + dt*I
            float2 k;
            k.x = (lif2.x > 1.0f) ? kC : 0.0f;     // FSETP+FSEL
            k.y = (lif2.y > 1.0f) ? kC : 0.0f;     // FSETP+FSEL
            lif2 = ffma2(k, CR2, lif2);            // soft reset (-1 per spike)
            hzs2 = ffma2(hzs2, EZ2, ffma2(GN2, hy2, k));
            hy2  = fadd2(hy2, hzs2);               // hy += dt*hz
            mx2.x = fmaxf(mx2.x, hy2.x);           // FMNMX
            mx2.y = fmaxf(mx2.y, hy2.y);           // FMNMX
        }
    }

    const bool ever = bar_red_or(fmaxf(mx2.x, mx2.y) > 1.0f);
    if (tid == 0) g_spiked[b] = ever ? 1 : 0;

    // Zero output (correct if no spike; fix kernel overwrites otherwise).
    float* o0 = out + (size_t)b * (2 * NHID) + tid * NPTC;
    const float2 z = make_float2(0.f, 0.f);
    ((float2*)o0)[0] = z;
    ((float2*)(o0 + NHID))[0] = z;
}

// ======================= FIX KERNEL (general coupled path) ================
// Full dynamics with recurrent h2h gather + ref/ft/fts, only for flagged rows
// (expected: none on this data; correctness safety net for any input).
__global__ __launch_bounds__(TPBF)
void coesn_fix(const float* __restrict__ x,
               const float* __restrict__ x2h,
               const float* __restrict__ h2h,
               const float* __restrict__ bias,
               const float* __restrict__ gamma_,
               const float* __restrict__ eps_,
               const float* __restrict__ sgain,
               float* __restrict__ out)
{
    const int b = blockIdx.x;
    if (g_spiked[b] == 0) return;      // uniform per CTA

    __shared__ float    xs[LSTEPS];
    __shared__ unsigned smask[TPBF];
    __shared__ float    sref[NHID], sft[NHID], sfts[NHID];

    const int tid = threadIdx.x;

    {
        const float4* xr = (const float4*)(x + (size_t)b * LSTEPS);
        ((float4*)xs)[tid]        = xr[tid];
        ((float4*)xs)[tid + TPBF] = xr[tid + TPBF];
    }

    const float dt = 0.01f;
    const float A  = 1.0f - dt / 20.0f;
    const float sg = *sgain;
    const float RD = expf(-dt / 0.25f);
    const float FD = expf(-dt / 10.0f);

    const float2 A2     = make_float2(A, A);
    const float2 DT2    = make_float2(dt, dt);
    const float2 NDTSG2 = make_float2(-dt * sg, -dt * sg);
    const float2 RD2    = make_float2(RD, RD);
    const float2 FD2    = make_float2(FD, FD);

    float2 W2[NPRF], B2[NPRF], EZ2[NPRF], GN2[NPRF];
    #pragma unroll
    for (int i = 0; i < 2; ++i) {
        float4 a;
        a = ((const float4*)x2h)[tid * 2 + i];
        W2[2*i]   = make_float2(dt*a.x, dt*a.y);
        W2[2*i+1] = make_float2(dt*a.z, dt*a.w);
        a = ((const float4*)bias)[tid * 2 + i];
        B2[2*i]   = make_float2(dt*a.x, dt*a.y);
        B2[2*i+1] = make_float2(dt*a.z, dt*a.w);
        a = ((const float4*)eps_)[tid * 2 + i];
        EZ2[2*i]   = make_float2(1.f-dt*a.x, 1.f-dt*a.y);
        EZ2[2*i+1] = make_float2(1.f-dt*a.z, 1.f-dt*a.w);
        a = ((const float4*)gamma_)[tid * 2 + i];
        GN2[2*i]   = make_float2(-dt*a.x, -dt*a.y);
        GN2[2*i+1] = make_float2(-dt*a.z, -dt*a.w);
    }

    float2 lif2[NPRF], hy2[NPRF], hz2[NPRF];
    #pragma unroll
    for (int p = 0; p < NPRF; ++p) {
        lif2[p] = make_float2(0.f, 0.f);
        hy2[p]  = make_float2(0.f, 0.f);
        hz2[p]  = make_float2(0.f, 0.f);
    }
    #pragma unroll
    for (int q = 0; q < NPTF; ++q) {
        const int n = tid * NPTF + q;
        sref[n] = 0.f; sft[n] = 0.f; sfts[n] = 0.f;
    }
    smask[tid] = 0u;
    __syncthreads();

    bool prev = false;
    #pragma unroll 1
    for (int t = 0; t < LSTEPS; ++t) {
        const float  xt  = xs[t];
        const float2 XT2 = make_float2(xt, xt);

        float2 acc[NPRF];
        #pragma unroll
        for (int p = 0; p < NPRF; ++p) acc[p] = make_float2(0.f, 0.f);

        if (prev) {
            for (int w = 0; w < TPBF; ++w) {
                unsigned mm_ = smask[w];
                while (mm_) {
                    const int k = __ffs(mm_) - 1; mm_ &= mm_ - 1;
                    const int j = w * NPTF + k;
                    const float4* hp =
                        (const float4*)(h2h + (size_t)j * NHID + tid * NPTF);
                    #pragma unroll
                    for (int i = 0; i < 2; ++i) {
                        float4 h = __ldg(hp + i);
                        acc[2*i].x   += h.x; acc[2*i].y   += h.y;
                        acc[2*i+1].x += h.z; acc[2*i+1].y += h.w;
                    }
                }
            }
        }

        bool any = false;
        unsigned msk = 0;
        #pragma unroll
        for (int p = 0; p < NPRF; ++p) {
            float2 I = ffma2(XT2, W2[p], B2[p]);
            I = ffma2(DT2, acc[p], I);
            lif2[p] = ffma2(lif2[p], A2, I);
            const bool l0 = lif2[p].x > 1.0f;
            const bool l1 = lif2[p].y > 1.0f;
            float2 ms = make_float2(l0 ? -1.0f : 0.0f, l1 ? -1.0f : 0.0f);
            lif2[p] = fadd2(lif2[p], ms);
            float2 k = fmul2(ms, NDTSG2);
            hz2[p] = ffma2(hz2[p], EZ2[p], ffma2(GN2[p], hy2[p], k));
            hy2[p] = ffma2(DT2, hz2[p], hy2[p]);

            const int n = tid * NPTF + 2 * p;
            float2 rf = make_float2(sref[n], sref[n+1]);
            const bool q0 = (hy2[p].x - 1.0f) > rf.x;
            const bool q1 = (hy2[p].y - 1.0f) > rf.y;
            float2 sn = make_float2(q0 ? 1.0f : 0.0f, q1 ? 1.0f : 0.0f);
            rf = ffma2(rf, RD2, sn);
            sref[n] = rf.x; sref[n+1] = rf.y;
            float2 f = make_float2(sft[n], sft[n+1]);
            f = ffma2(f, FD2, sn);
            sft[n] = f.x; sft[n+1] = f.y;
            sfts[n]   += f.x;
            sfts[n+1] += f.y;
            any = any || q0 || q1;
            msk |= (q0 ? 1u : 0u) << (2 * p);
            msk |= (q1 ? 1u : 0u) << (2 * p + 1);
        }
        smask[tid] = msk;
        prev = bar_red_or(any);
    }

    const float invL = 1.0f / (float)LSTEPS;
    float* o0 = out + (size_t)b * (2 * NHID) + tid * NPTF;
    float* o1 = o0 + NHID;
    #pragma unroll
    for (int i = 0; i < 2; ++i) {
        const int n = tid * NPTF + 4 * i;
        ((float4*)o0)[i] = make_float4(sfts[n]*invL, sfts[n+1]*invL,
                                       sfts[n+2]*invL, sfts[n+3]*invL);
        ((float4*)o1)[i] = make_float4(sft[n], sft[n+1], sft[n+2], sft[n+3]);
    }
}

extern "C" void kernel_launch(void* const* d_in, const int* in_sizes, int n_in,
                              void* d_out, int out_size)
{
    const float* x    = (const float*)d_in[0];
    const float* x2h  = (const float*)d_in[1];
    const float* h2h  = (const float*)d_in[2];
    const float* bias = (const float*)d_in[3];
    const float* gam  = (const float*)d_in[4];
    const float* eps  = (const float*)d_in[5];
    const float* sg   = (const float*)d_in[6];

    const int B = in_sizes[0] / LSTEPS;   // N_INP == 1
    coesn_cold<<<B, TPBC>>>(x, x2h, bias, gam, eps, sg, (float*)d_out);
    coesn_fix <<<B, TPBF>>>(x, x2h, h2h, bias, gam, eps, sg, (float*)d_out);
}

// round 14
// speedup vs baseline: 1.0246x; 1.0246x over previous
#include <cuda_runtime.h>
#include <cstdint>
#include <math.h>

#define NHID   1024
#define LSTEPS 1024
#define TPBC   256          // cold kernel: 8 warps per CTA, one CTA per row
#define NPTC   4            // cold: neurons per thread
#define NPRC   2            // cold: f32x2 pairs per thread
#define TPBF   128          // fix kernel
#define NPTF   8
#define NPRF   4
#define BMAX   4096

typedef unsigned long long u64;

__device__ int g_spiked[BMAX];   // per-row "any RF spike ever" flag

// ---- packed f32x2 ops (sm_100+) ----
__device__ __forceinline__ float2 ffma2(float2 a, float2 b, float2 c) {
    float2 d;
    asm("fma.rn.f32x2 %0, %1, %2, %3;"
        : "=l"(*(u64*)&d) : "l"(*(u64*)&a), "l"(*(u64*)&b), "l"(*(u64*)&c));
    return d;
}
__device__ __forceinline__ float2 fadd2(float2 a, float2 b) {
    float2 d;
    asm("add.rn.f32x2 %0, %1, %2;"
        : "=l"(*(u64*)&d) : "l"(*(u64*)&a), "l"(*(u64*)&b));
    return d;
}
__device__ __forceinline__ float2 fmul2(float2 a, float2 b) {
    float2 d;
    asm("mul.rn.f32x2 %0, %1, %2;"
        : "=l"(*(u64*)&d) : "l"(*(u64*)&a), "l"(*(u64*)&b));
    return d;
}

// Barrier + OR-reduction across the CTA in one BAR.RED instruction.
__device__ __forceinline__ bool bar_red_or(bool p) {
    unsigned r;
    asm volatile(
        "{\n\t"
        ".reg .pred pi, po;\n\t"
        "setp.ne.u32 pi, %1, 0;\n\t"
        "bar.red.or.pred po, 0, pi;\n\t"
        "selp.u32 %0, 1, 0, po;\n\t"
        "}"
        : "=r"(r) : "r"((unsigned)p) : "memory");
    return r != 0;
}

// ======================= COLD KERNEL (barrier-free mainloop) ==============
// While no RF spike has EVER occurred in a row, ref/ft/fts are exactly 0 and
// there is no recurrent coupling; alpha=beta=0 means an RF spike would not
// alter hy/hz. The uncoupled lif/hy/hzs trajectory is valid up to and
// including the first crossing; "did any neuron ever cross hy>1" (ref==0 =>
// spike cond (hy-1-ref)>0 <=> hy>1, Sterbenz-exact) decides everything.
// hzs = dt*hz:  hzs' = hzs*(1-dt*eps) + (-dt^2*gamma)*hy + k;  hy += hzs'.
// k = (lif>1) ? dt^2*sg : 0; reset: lif += k*(-1/(dt^2*sg)) == -spike (1 ulp).
//
// RF-banking-aware fma-pipe budget per pair-step (rt = #distinct reg pairs):
//   I      ffma2(XT2,W2,B2)        rt3
//   lif.x  FFMA-imm (A=0.9995f)    rt1   <- literal multiplier, imm form
//   lif.y  FFMA-imm                rt1
//   reset  ffma2(k,CR2,lif)        rt3   (CR runtime -> no imm form)
//   inner  ffma2(GN2,hy,k)         rt3
//   outer  ffma2(hzs,EZ2,inner)    rt3
//   hyadd  fadd2                   rt2      => 16 cyc (was 17)
// alu: FSETP x2 + FSEL x2 + FMNMX x2 = 12 cyc. fma-bound at 16.
__global__ __launch_bounds__(TPBC, 6)
void coesn_cold(const float* __restrict__ x,      // (B, L)
                const float* __restrict__ x2h,    // (NHID)
                const float* __restrict__ bias,   // (NHID)
                const float* __restrict__ gamma_, // (NHID)
                const float* __restrict__ eps_,   // (NHID)
                const float* __restrict__ sgain,  // scalar
                float* __restrict__ out)          // (B, 2*NHID)
{
    __shared__ float xs2[2 * LSTEPS];   // duplicated: xs2[2t]=xs2[2t+1]=x[t]

    const int tid = threadIdx.x;
    const int b   = blockIdx.x;

    // Stage duplicated input: each thread expands one float4 (4 steps).
    {
        const float4 v = ((const float4*)(x + (size_t)b * LSTEPS))[tid];
        float4* dst = ((float4*)xs2) + 2 * tid;
        dst[0] = make_float4(v.x, v.x, v.y, v.y);
        dst[1] = make_float4(v.z, v.z, v.w, v.w);
    }

    const float dt = 0.01f;
    const float kC = dt * dt * (*sgain);            // hzs kick per LIF spike
    const float2 CR2 = make_float2(-1.0f / kC, -1.0f / kC);  // reset scale

    float2 W2[NPRC], B2[NPRC], EZ2[NPRC], GN2[NPRC];
    {
        float4 a;
        a = ((const float4*)x2h)[tid];
        W2[0] = make_float2(dt*a.x, dt*a.y);  W2[1] = make_float2(dt*a.z, dt*a.w);
        a = ((const float4*)bias)[tid];
        B2[0] = make_float2(dt*a.x, dt*a.y);  B2[1] = make_float2(dt*a.z, dt*a.w);
        a = ((const float4*)eps_)[tid];
        EZ2[0] = make_float2(1.f-dt*a.x, 1.f-dt*a.y);
        EZ2[1] = make_float2(1.f-dt*a.z, 1.f-dt*a.w);
        a = ((const float4*)gamma_)[tid];
        GN2[0] = make_float2(-dt*dt*a.x, -dt*dt*a.y);
        GN2[1] = make_float2(-dt*dt*a.z, -dt*dt*a.w);
    }

    float2 lif2[NPRC], hy2[NPRC], hzs2[NPRC];
    #pragma unroll
    for (int p = 0; p < NPRC; ++p) {
        lif2[p] = make_float2(0.f, 0.f);
        hy2[p]  = make_float2(0.f, 0.f);
        hzs2[p] = make_float2(0.f, 0.f);
    }
    float2 mx2 = make_float2(-1.f, -1.f);   // running max of hy (both lanes)

    __syncthreads();   // xs2 ready

    const float4* xv = (const float4*)xs2;   // one float4 = 2 duplicated steps
    #pragma unroll 1
    for (int it = 0; it < LSTEPS / 8; ++it) {
        float4 q[4];
        #pragma unroll
        for (int i = 0; i < 4; ++i) q[i] = xv[it * 4 + i];   // 8 steps of pairs
        #pragma unroll
        for (int s = 0; s < 8; ++s) {
            const float* qf = (const float*)q;
            const float2 XT2 = make_float2(qf[2 * s], qf[2 * s + 1]);
            #pragma unroll
            for (int p = 0; p < NPRC; ++p) {
                float2 I = ffma2(XT2, W2[p], B2[p]);         // rt3
                // lif = lif*A + I with literal A -> FFMA-imm (rt1) per lane
                lif2[p].x = fmaf(lif2[p].x, 0.9995f, I.x);   // rt1
                lif2[p].y = fmaf(lif2[p].y, 0.9995f, I.y);   // rt1
                float2 k;
                k.x = (lif2[p].x > 1.0f) ? kC : 0.0f;        // FSETP+FSEL
                k.y = (lif2[p].y > 1.0f) ? kC : 0.0f;        // FSETP+FSEL
                lif2[p] = ffma2(k, CR2, lif2[p]);            // soft reset rt3
                hzs2[p] = ffma2(hzs2[p], EZ2[p], ffma2(GN2[p], hy2[p], k));
                hy2[p]  = fadd2(hy2[p], hzs2[p]);            // rt2
                mx2.x = fmaxf(mx2.x, hy2[p].x);              // FMNMX
                mx2.y = fmaxf(mx2.y, hy2[p].y);              // FMNMX
            }
        }
    }

    const bool ever = bar_red_or(fmaxf(mx2.x, mx2.y) > 1.0f);
    if (tid == 0) g_spiked[b] = ever ? 1 : 0;

    // Zero output (correct if no spike; fix kernel overwrites otherwise).
    float* o0 = out + (size_t)b * (2 * NHID) + tid * NPTC;
    const float4 z = make_float4(0.f, 0.f, 0.f, 0.f);
    ((float4*)o0)[0] = z;
    ((float4*)(o0 + NHID))[0] = z;
}

// ======================= FIX KERNEL (general coupled path) ================
// Full dynamics with recurrent h2h gather + ref/ft/fts, only for flagged rows
// (expected: none on this data; correctness safety net for any input).
__global__ __launch_bounds__(TPBF)
void coesn_fix(const float* __restrict__ x,
               const float* __restrict__ x2h,
               const float* __restrict__ h2h,
               const float* __restrict__ bias,
               const float* __restrict__ gamma_,
               const float* __restrict__ eps_,
               const float* __restrict__ sgain,
               float* __restrict__ out)
{
    const int b = blockIdx.x;
    if (g_spiked[b] == 0) return;      // uniform per CTA

    __shared__ float    xs[LSTEPS];
    __shared__ unsigned smask[TPBF];
    __shared__ float    sref[NHID], sft[NHID], sfts[NHID];

    const int tid = threadIdx.x;

    {
        const float4* xr = (const float4*)(x + (size_t)b * LSTEPS);
        ((float4*)xs)[tid]        = xr[tid];
        ((float4*)xs)[tid + TPBF] = xr[tid + TPBF];
    }

    const float dt = 0.01f;
    const float A  = 1.0f - dt / 20.0f;
    const float sg = *sgain;
    const float RD = expf(-dt / 0.25f);
    const float FD = expf(-dt / 10.0f);

    const float2 A2     = make_float2(A, A);
    const float2 DT2    = make_float2(dt, dt);
    const float2 NDTSG2 = make_float2(-dt * sg, -dt * sg);
    const float2 RD2    = make_float2(RD, RD);
    const float2 FD2    = make_float2(FD, FD);

    float2 W2[NPRF], B2[NPRF], EZ2[NPRF], GN2[NPRF];
    #pragma unroll
    for (int i = 0; i < 2; ++i) {
        float4 a;
        a = ((const float4*)x2h)[tid * 2 + i];
        W2[2*i]   = make_float2(dt*a.x, dt*a.y);
        W2[2*i+1] = make_float2(dt*a.z, dt*a.w);
        a = ((const float4*)bias)[tid * 2 + i];
        B2[2*i]   = make_float2(dt*a.x, dt*a.y);
        B2[2*i+1] = make_float2(dt*a.z, dt*a.w);
        a = ((const float4*)eps_)[tid * 2 + i];
        EZ2[2*i]   = make_float2(1.f-dt*a.x, 1.f-dt*a.y);
        EZ2[2*i+1] = make_float2(1.f-dt*a.z, 1.f-dt*a.w);
        a = ((const float4*)gamma_)[tid * 2 + i];
        GN2[2*i]   = make_float2(-dt*a.x, -dt*a.y);
        GN2[2*i+1] = make_float2(-dt*a.z, -dt*a.w);
    }

    float2 lif2[NPRF], hy2[NPRF], hz2[NPRF];
    #pragma unroll
    for (int p = 0; p < NPRF; ++p) {
        lif2[p] = make_float2(0.f, 0.f);
        hy2[p]  = make_float2(0.f, 0.f);
        hz2[p]  = make_float2(0.f, 0.f);
    }
    #pragma unroll
    for (int q = 0; q < NPTF; ++q) {
        const int n = tid * NPTF + q;
        sref[n] = 0.f; sft[n] = 0.f; sfts[n] = 0.f;
    }
    smask[tid] = 0u;
    __syncthreads();

    bool prev = false;
    #pragma unroll 1
    for (int t = 0; t < LSTEPS; ++t) {
        const float  xt  = xs[t];
        const float2 XT2 = make_float2(xt, xt);

        float2 acc[NPRF];
        #pragma unroll
        for (int p = 0; p < NPRF; ++p) acc[p] = make_float2(0.f, 0.f);

        if (prev) {
            for (int w = 0; w < TPBF; ++w) {
                unsigned mm_ = smask[w];
                while (mm_) {
                    const int k = __ffs(mm_) - 1; mm_ &= mm_ - 1;
                    const int j = w * NPTF + k;
                    const float4* hp =
                        (const float4*)(h2h + (size_t)j * NHID + tid * NPTF);
                    #pragma unroll
                    for (int i = 0; i < 2; ++i) {
                        float4 h = __ldg(hp + i);
                        acc[2*i].x   += h.x; acc[2*i].y   += h.y;
                        acc[2*i+1].x += h.z; acc[2*i+1].y += h.w;
                    }
                }
            }
        }

        bool any = false;
        unsigned msk = 0;
        #pragma unroll
        for (int p = 0; p < NPRF; ++p) {
            float2 I = ffma2(XT2, W2[p], B2[p]);
            I = ffma2(DT2, acc[p], I);
            lif2[p] = ffma2(lif2[p], A2, I);
            const bool l0 = lif2[p].x > 1.0f;
            const bool l1 = lif2[p].y > 1.0f;
            float2 ms = make_float2(l0 ? -1.0f : 0.0f, l1 ? -1.0f : 0.0f);
            lif2[p] = fadd2(lif2[p], ms);
            float2 k = fmul2(ms, NDTSG2);
            hz2[p] = ffma2(hz2[p], EZ2[p], ffma2(GN2[p], hy2[p], k));
            hy2[p] = ffma2(DT2, hz2[p], hy2[p]);

            const int n = tid * NPTF + 2 * p;
            float2 rf = make_float2(sref[n], sref[n+1]);
            const bool q0 = (hy2[p].x - 1.0f) > rf.x;
            const bool q1 = (hy2[p].y - 1.0f) > rf.y;
            float2 sn = make_float2(q0 ? 1.0f : 0.0f, q1 ? 1.0f : 0.0f);
            rf = ffma2(rf, RD2, sn);
            sref[n] = rf.x; sref[n+1] = rf.y;
            float2 f = make_float2(sft[n], sft[n+1]);
            f = ffma2(f, FD2, sn);
            sft[n] = f.x; sft[n+1] = f.y;
            sfts[n]   += f.x;
            sfts[n+1] += f.y;
            any = any || q0 || q1;
            msk |= (q0 ? 1u : 0u) << (2 * p);
            msk |= (q1 ? 1u : 0u) << (2 * p + 1);
        }
        smask[tid] = msk;
        prev = bar_red_or(any);
    }

    const float invL = 1.0f / (float)LSTEPS;
    float* o0 = out + (size_t)b * (2 * NHID) + tid * NPTF;
    float* o1 = o0 + NHID;
    #pragma unroll
    for (int i = 0; i < 2; ++i) {
        const int n = tid * NPTF + 4 * i;
        ((float4*)o0)[i] = make_float4(sfts[n]*invL, sfts[n+1]*invL,
                                       sfts[n+2]*invL, sfts[n+3]*invL);
        ((float4*)o1)[i] = make_float4(sft[n], sft[n+1], sft[n+2], sft[n+3]);
    }
}

extern "C" void kernel_launch(void* const* d_in, const int* in_sizes, int n_in,
                              void* d_out, int out_size)
{
    const float* x    = (const float*)d_in[0];
    const float* x2h  = (const float*)d_in[1];
    const float* h2h  = (const float*)d_in[2];
    const float* bias = (const float*)d_in[3];
    const float* gam  = (const float*)d_in[4];
    const float* eps  = (const float*)d_in[5];
    const float* sg   = (const float*)d_in[6];

    const int B = in_sizes[0] / LSTEPS;   // N_INP == 1
    coesn_cold<<<B, TPBC>>>(x, x2h, bias, gam, eps, sg, (float*)d_out);
    coesn_fix <<<B, TPBF>>>(x, x2h, h2h, bias, gam, eps, sg, (float*)d_out);
}

// round 15
// speedup vs baseline: 1.3373x; 1.3052x over previous
#include <cuda_runtime.h>
#include <cstdint>
#include <math.h>

#define NHID   1024
#define LSTEPS 1024
#define TPBC   256          // cold kernel: 8 warps per CTA, one CTA per row
#define NPTC   4            // cold: neurons per thread
#define NPRC   2            // cold: f32x2 pairs per thread
#define TPBF   128          // fix kernel
#define NPTF   8
#define NPRF   4
#define BMAX   4096

typedef unsigned long long u64;

__device__ int g_spiked[BMAX];   // per-row "needs exact path" flag

// ---- packed f32x2 ops (sm_100+) ----
__device__ __forceinline__ float2 ffma2(float2 a, float2 b, float2 c) {
    float2 d;
    asm("fma.rn.f32x2 %0, %1, %2, %3;"
        : "=l"(*(u64*)&d) : "l"(*(u64*)&a), "l"(*(u64*)&b), "l"(*(u64*)&c));
    return d;
}
__device__ __forceinline__ float2 fadd2(float2 a, float2 b) {
    float2 d;
    asm("add.rn.f32x2 %0, %1, %2;"
        : "=l"(*(u64*)&d) : "l"(*(u64*)&a), "l"(*(u64*)&b));
    return d;
}
__device__ __forceinline__ float2 fmul2(float2 a, float2 b) {
    float2 d;
    asm("mul.rn.f32x2 %0, %1, %2;"
        : "=l"(*(u64*)&d) : "l"(*(u64*)&a), "l"(*(u64*)&b));
    return d;
}

// Barrier + OR-reduction across the CTA in one BAR.RED instruction.
__device__ __forceinline__ bool bar_red_or(bool p) {
    unsigned r;
    asm volatile(
        "{\n\t"
        ".reg .pred pi, po;\n\t"
        "setp.ne.u32 pi, %1, 0;\n\t"
        "bar.red.or.pred po, 0, pi;\n\t"
        "selp.u32 %0, 1, 0, po;\n\t"
        "}"
        : "=r"(r) : "r"((unsigned)p) : "memory");
    return r != 0;
}

// ======================= COLD KERNEL (sound spike-bound screen) ===========
// Writes zeros + a per-row flag. The flag is a SOUND OVER-APPROXIMATION of
// "some RF spike occurred": if the flag stays 0, the true output is exactly
// zeros; if it trips (even spuriously), the fix kernel recomputes the row
// with the full exact dynamics. Correct for every input.
//
// Soundness argument. Before any RF spike, ref/ft/fts==0 and there is no
// recurrent coupling, so the LIF trajectory is exact (simulated below).
// The RF pair (hz,hy) is LINEAR between LIF kicks. For the reference's
// semi-implicit update   hz' = (1-dt e)hz - dt g hy + dt sg s ;
// hy' = hy + dt hz'   the 2x2 matrix M has complex eigenvalues of modulus
// |l| = sqrt(1-dt e)  (det = 1-dt e; complex since e^2 < 4g on the guarded
// range e in [1,2], g in [2,3]).  The exact power formula gives
//   |(M^D)_{hy<-hz}| = |l|^{D-1} |sin(D q)/sin q| dt(1-dt e) <= 0.0102 |l|^D/w_d... 
// with w_d = sqrt(g - e^2/4) >= 1, this yields per-unit-impulse response
//   |hy_t| <= (dt*sg/w_d)*1.02*|l|^{t-s} <= 0.0311 * lbar^{t-s},
// lbar = sqrt(1-dt*1) = 0.99499 >= |l| for all e >= 1. By superposition,
//   |hy_t| <= 0.0311 * W_t,   W_t = lbar*W_{t-1} + s_t.
// An RF spike needs hy>1, impossible while W < 32. We flag at W > 9.6
// (3x margin; window-end checking adds lbar^-8 = 1.0415, folded in).
// Guards force the flag whenever e,g,sg leave the assumed ranges.
//
// Body per pair-step: fma = I(rt3) + 2x lif FFMA-imm(rt1) + reset fadd2(rt2)
// + 2x W FFMA-imm(rt1) = 9 cyc;  alu = FSETP x2 + FSEL x2 = 8 cyc
// (+ 6 FMNMX per 8-step window, amortized 0.4).
__global__ __launch_bounds__(TPBC, 6)
void coesn_cold(const float* __restrict__ x,      // (B, L)
                const float* __restrict__ x2h,    // (NHID)
                const float* __restrict__ bias,   // (NHID)
                const float* __restrict__ gamma_, // (NHID)
                const float* __restrict__ eps_,   // (NHID)
                const float* __restrict__ sgain,  // scalar
                float* __restrict__ out)          // (B, 2*NHID)
{
    __shared__ float xs2[2 * LSTEPS];   // duplicated: xs2[2t]=xs2[2t+1]=x[t]

    const int tid = threadIdx.x;
    const int b   = blockIdx.x;

    // Stage duplicated input: each thread expands one float4 (4 steps).
    {
        const float4 v = ((const float4*)(x + (size_t)b * LSTEPS))[tid];
        float4* dst = ((float4*)xs2) + 2 * tid;
        dst[0] = make_float4(v.x, v.x, v.y, v.y);
        dst[1] = make_float4(v.z, v.z, v.w, v.w);
    }

    const float dt   = 0.01f;
    const float A    = 1.0f - dt / 20.0f;     // LIF decay (literal -> FFMA-imm)
    const float LAMB = 0.99499f;              // >= sqrt(1-dt*eps) for eps>=1
    const float THRW = 9.6f;                  // 10 / lbar^-8, W flag threshold

    // Parameter-range guard: outside the proven range -> force exact path.
    bool bad;
    {
        const float sg = *sgain;
        float4 e = ((const float4*)eps_)[tid];
        float4 g = ((const float4*)gamma_)[tid];
        bad = !(sg >= 0.0f && sg <= 3.0001f)
           || !(e.x >= 1.0f && e.x <= 2.0001f) || !(e.y >= 1.0f && e.y <= 2.0001f)
           || !(e.z >= 1.0f && e.z <= 2.0001f) || !(e.w >= 1.0f && e.w <= 2.0001f)
           || !(g.x >= 2.0f && g.x <= 3.0001f) || !(g.y >= 2.0f && g.y <= 3.0001f)
           || !(g.z >= 2.0f && g.z <= 3.0001f) || !(g.w >= 2.0f && g.w <= 3.0001f);
    }

    float2 W2[NPRC], B2[NPRC];
    {
        float4 a;
        a = ((const float4*)x2h)[tid];
        W2[0] = make_float2(dt*a.x, dt*a.y);  W2[1] = make_float2(dt*a.z, dt*a.w);
        a = ((const float4*)bias)[tid];
        B2[0] = make_float2(dt*a.x, dt*a.y);  B2[1] = make_float2(dt*a.z, dt*a.w);
    }

    float2 lif2[NPRC], Wn2[NPRC];       // Wn accumulates NEGATIVE spikes
    #pragma unroll
    for (int p = 0; p < NPRC; ++p) {
        lif2[p] = make_float2(0.f, 0.f);
        Wn2[p]  = make_float2(0.f, 0.f);
    }
    float2 wmin2 = make_float2(0.f, 0.f);   // running min of Wn (window ends)

    __syncthreads();   // xs2 ready

    const float4* xv = (const float4*)xs2;   // one float4 = 2 duplicated steps
    #pragma unroll 1
    for (int it = 0; it < LSTEPS / 8; ++it) {
        float4 q[4];
        #pragma unroll
        for (int i = 0; i < 4; ++i) q[i] = xv[it * 4 + i];   // 8 steps of pairs
        #pragma unroll
        for (int s = 0; s < 8; ++s) {
            const float* qf = (const float*)q;
            const float2 XT2 = make_float2(qf[2 * s], qf[2 * s + 1]);
            #pragma unroll
            for (int p = 0; p < NPRC; ++p) {
                float2 I = ffma2(XT2, W2[p], B2[p]);           // rt3
                lif2[p].x = fmaf(lif2[p].x, A, I.x);           // FFMA-imm rt1
                lif2[p].y = fmaf(lif2[p].y, A, I.y);           // FFMA-imm rt1
                float2 ms;
                ms.x = (lif2[p].x > 1.0f) ? -1.0f : 0.0f;      // FSETP+FSEL
                ms.y = (lif2[p].y > 1.0f) ? -1.0f : 0.0f;      // FSETP+FSEL
                lif2[p] = fadd2(lif2[p], ms);                  // reset rt2
                Wn2[p].x = fmaf(Wn2[p].x, LAMB, ms.x);         // FFMA-imm rt1
                Wn2[p].y = fmaf(Wn2[p].y, LAMB, ms.y);         // FFMA-imm rt1
            }
        }
        // Window-end check (lbar^-8 slack folded into THRW): W only deepens
        // at spike steps and decays toward 0 otherwise, so window-end min
        // bounds the in-window min within a factor lbar^-8.
        wmin2.x = fminf(wmin2.x, fminf(Wn2[0].x, Wn2[1].x));
        wmin2.y = fminf(wmin2.y, fminf(Wn2[0].y, Wn2[1].y));
    }

    const bool fire = (fminf(wmin2.x, wmin2.y) < -THRW) || bad;
    const bool ever = bar_red_or(fire);
    if (tid == 0) g_spiked[b] = ever ? 1 : 0;

    // Zero output (correct if no spike; fix kernel overwrites otherwise).
    float* o0 = out + (size_t)b * (2 * NHID) + tid * NPTC;
    const float4 z = make_float4(0.f, 0.f, 0.f, 0.f);
    ((float4*)o0)[0] = z;
    ((float4*)(o0 + NHID))[0] = z;
}

// ======================= FIX KERNEL (general coupled path) ================
// Full exact dynamics with recurrent h2h gather + ref/ft/fts, only for
// flagged rows (expected: none on this data; correctness net for any input).
__global__ __launch_bounds__(TPBF)
void coesn_fix(const float* __restrict__ x,
               const float* __restrict__ x2h,
               const float* __restrict__ h2h,
               const float* __restrict__ bias,
               const float* __restrict__ gamma_,
               const float* __restrict__ eps_,
               const float* __restrict__ sgain,
               float* __restrict__ out)
{
    const int b = blockIdx.x;
    if (g_spiked[b] == 0) return;      // uniform per CTA

    __shared__ float    xs[LSTEPS];
    __shared__ unsigned smask[TPBF];
    __shared__ float    sref[NHID], sft[NHID], sfts[NHID];

    const int tid = threadIdx.x;

    {
        const float4* xr = (const float4*)(x + (size_t)b * LSTEPS);
        ((float4*)xs)[tid]        = xr[tid];
        ((float4*)xs)[tid + TPBF] = xr[tid + TPBF];
    }

    const float dt = 0.01f;
    const float A  = 1.0f - dt / 20.0f;
    const float sg = *sgain;
    const float RD = expf(-dt / 0.25f);
    const float FD = expf(-dt / 10.0f);

    const float2 A2     = make_float2(A, A);
    const float2 DT2    = make_float2(dt, dt);
    const float2 NDTSG2 = make_float2(-dt * sg, -dt * sg);
    const float2 RD2    = make_float2(RD, RD);
    const float2 FD2    = make_float2(FD, FD);

    float2 W2[NPRF], B2[NPRF], EZ2[NPRF], GN2[NPRF];
    #pragma unroll
    for (int i = 0; i < 2; ++i) {
        float4 a;
        a = ((const float4*)x2h)[tid * 2 + i];
        W2[2*i]   = make_float2(dt*a.x, dt*a.y);
        W2[2*i+1] = make_float2(dt*a.z, dt*a.w);
        a = ((const float4*)bias)[tid * 2 + i];
        B2[2*i]   = make_float2(dt*a.x, dt*a.y);
        B2[2*i+1] = make_float2(dt*a.z, dt*a.w);
        a = ((const float4*)eps_)[tid * 2 + i];
        EZ2[2*i]   = make_float2(1.f-dt*a.x, 1.f-dt*a.y);
        EZ2[2*i+1] = make_float2(1.f-dt*a.z, 1.f-dt*a.w);
        a = ((const float4*)gamma_)[tid * 2 + i];
        GN2[2*i]   = make_float2(-dt*a.x, -dt*a.y);
        GN2[2*i+1] = make_float2(-dt*a.z, -dt*a.w);
    }

    float2 lif2[NPRF], hy2[NPRF], hz2[NPRF];
    #pragma unroll
    for (int p = 0; p < NPRF; ++p) {
        lif2[p] = make_float2(0.f, 0.f);
        hy2[p]  = make_float2(0.f, 0.f);
        hz2[p]  = make_float2(0.f, 0.f);
    }
    #pragma unroll
    for (int q = 0; q < NPTF; ++q) {
        const int n = tid * NPTF + q;
        sref[n] = 0.f; sft[n] = 0.f; sfts[n] = 0.f;
    }
    smask[tid] = 0u;
    __syncthreads();

    bool prev = false;
    #pragma unroll 1
    for (int t = 0; t < LSTEPS; ++t) {
        const float  xt  = xs[t];
        const float2 XT2 = make_float2(xt, xt);

        float2 acc[NPRF];
        #pragma unroll
        for (int p = 0; p < NPRF; ++p) acc[p] = make_float2(0.f, 0.f);

        if (prev) {
            for (int w = 0; w < TPBF; ++w) {
                unsigned mm_ = smask[w];
                while (mm_) {
                    const int k = __ffs(mm_) - 1; mm_ &= mm_ - 1;
                    const int j = w * NPTF + k;
                    const float4* hp =
                        (const float4*)(h2h + (size_t)j * NHID + tid * NPTF);
                    #pragma unroll
                    for (int i = 0; i < 2; ++i) {
                        float4 h = __ldg(hp + i);
                        acc[2*i].x   += h.x; acc[2*i].y   += h.y;
                        acc[2*i+1].x += h.z; acc[2*i+1].y += h.w;
                    }
                }
            }
        }

        bool any = false;
        unsigned msk = 0;
        #pragma unroll
        for (int p = 0; p < NPRF; ++p) {
            float2 I = ffma2(XT2, W2[p], B2[p]);
            I = ffma2(DT2, acc[p], I);
            lif2[p] = ffma2(lif2[p], A2, I);
            const bool l0 = lif2[p].x > 1.0f;
            const bool l1 = lif2[p].y > 1.0f;
            float2 ms = make_float2(l0 ? -1.0f : 0.0f, l1 ? -1.0f : 0.0f);
            lif2[p] = fadd2(lif2[p], ms);
            float2 k = fmul2(ms, NDTSG2);
            hz2[p] = ffma2(hz2[p], EZ2[p], ffma2(GN2[p], hy2[p], k));
            hy2[p] = ffma2(DT2, hz2[p], hy2[p]);

            const int n = tid * NPTF + 2 * p;
            float2 rf = make_float2(sref[n], sref[n+1]);
            const bool q0 = (hy2[p].x - 1.0f) > rf.x;
            const bool q1 = (hy2[p].y - 1.0f) > rf.y;
            float2 sn = make_float2(q0 ? 1.0f : 0.0f, q1 ? 1.0f : 0.0f);
            rf = ffma2(rf, RD2, sn);
            sref[n] = rf.x; sref[n+1] = rf.y;
            float2 f = make_float2(sft[n], sft[n+1]);
            f = ffma2(f, FD2, sn);
            sft[n] = f.x; sft[n+1] = f.y;
            sfts[n]   += f.x;
            sfts[n+1] += f.y;
            any = any || q0 || q1;
            msk |= (q0 ? 1u : 0u) << (2 * p);
            msk |= (q1 ? 1u : 0u) << (2 * p + 1);
        }
        smask[tid] = msk;
        prev = bar_red_or(any);
    }

    const float invL = 1.0f / (float)LSTEPS;
    float* o0 = out + (size_t)b * (2 * NHID) + tid * NPTF;
    float* o1 = o0 + NHID;
    #pragma unroll
    for (int i = 0; i < 2; ++i) {
        const int n = tid * NPTF + 4 * i;
        ((float4*)o0)[i] = make_float4(sfts[n]*invL, sfts[n+1]*invL,
                                       sfts[n+2]*invL, sfts[n+3]*invL);
        ((float4*)o1)[i] = make_float4(sft[n], sft[n+1], sft[n+2], sft[n+3]);
    }
}

extern "C" void kernel_launch(void* const* d_in, const int* in_sizes, int n_in,
                              void* d_out, int out_size)
{
    const float* x    = (const float*)d_in[0];
    const float* x2h  = (const float*)d_in[1];
    const float* h2h  = (const float*)d_in[2];
    const float* bias = (const float*)d_in[3];
    const float* gam  = (const float*)d_in[4];
    const float* eps  = (const float*)d_in[5];
    const float* sg   = (const float*)d_in[6];

    const int B = in_sizes[0] / LSTEPS;   // N_INP == 1
    coesn_cold<<<B, TPBC>>>(x, x2h, bias, gam, eps, sg, (float*)d_out);
    coesn_fix <<<B, TPBF>>>(x, x2h, h2h, bias, gam, eps, sg, (float*)d_out);
}

// round 17
// speedup vs baseline: 46.4375x; 34.7250x over previous
#include <cuda_runtime.h>
#include <cstdint>
#include <math.h>

#define NHID   1024
#define LSTEPS 1024
#define TPBC   256          // cold kernel: 8 warps per CTA, one CTA per row
#define NPTC   4            // cold: neurons per thread
#define NWIN   8            // windows per row
#define WSTEP  128          // steps per window
#define TPBF   128          // fix kernel
#define NPTF   8
#define NPRF   4
#define BMAX   4096

typedef unsigned long long u64;

__device__ int g_spiked[BMAX];   // per-row "needs exact path" flag

// ---- packed f32x2 ops (sm_100+) ----
__device__ __forceinline__ float2 ffma2(float2 a, float2 b, float2 c) {
    float2 d;
    asm("fma.rn.f32x2 %0, %1, %2, %3;"
        : "=l"(*(u64*)&d) : "l"(*(u64*)&a), "l"(*(u64*)&b), "l"(*(u64*)&c));
    return d;
}
__device__ __forceinline__ float2 fadd2(float2 a, float2 b) {
    float2 d;
    asm("add.rn.f32x2 %0, %1, %2;"
        : "=l"(*(u64*)&d) : "l"(*(u64*)&a), "l"(*(u64*)&b));
    return d;
}
__device__ __forceinline__ float2 fmul2(float2 a, float2 b) {
    float2 d;
    asm("mul.rn.f32x2 %0, %1, %2;"
        : "=l"(*(u64*)&d) : "l"(*(u64*)&a), "l"(*(u64*)&b));
    return d;
}

// Barrier + OR-reduction across the CTA in one BAR.RED instruction.
__device__ __forceinline__ bool bar_red_or(bool p) {
    unsigned r;
    asm volatile(
        "{\n\t"
        ".reg .pred pi, po;\n\t"
        "setp.ne.u32 pi, %1, 0;\n\t"
        "bar.red.or.pred po, 0, pi;\n\t"
        "selp.u32 %0, 1, 0, po;\n\t"
        "}"
        : "=r"(r) : "r"((unsigned)p) : "memory");
    return r != 0;
}

// ======================= COLD KERNEL (window-level sound screen) ==========
// Writes zeros + a per-row flag that SOUNDLY over-approximates "some RF
// spike occurred". Unflagged rows provably output exactly zeros; flagged
// rows are recomputed exactly by the fix kernel. No per-step loop at all.
//
// Soundness chain (carried post-reset LIF state L, I_t = dt*(x_t*w + b)):
//  (1) L_t <= 1 + Imax for all t, Imax = dt*(b^+ + |w|*max|x|), provided
//      Imax <= 1 (induction: pre <= 1+2*Imax; post-reset <= 2*Imax <= 1+Imax;
//      no-spike <= 1). Guard: Imax > 0.9 -> flag.
//  (2) V = max(L,0) obeys V_t + s_t <= V_{t-1} + I_t^+  =>  spikes in any
//      window N <= V_start + sum I^+ <= (1+Imax) + dt*(D*b^+ + |w|*sum|x|).
//  (3) RF impulse response (semi-implicit update, eps in [1,2], gam in [2,3]):
//      eigenmodulus <= lam = sqrt(1-dt) = 0.99499, omega_d >= 1, so
//      hy_t <= 0.033 * W_t with W_t = sum lam^(t-s) s_s; an RF spike needs
//      hy > 1+ref >= 1, i.e. W >= 30.
//  (4) Per-window recurrence V_k = lam^D * V_{k-1} + N_k (D=128,
//      lam^128 <= 0.526) satisfies W_t <= lam^-D * V_k = 1.90*V_k for t in
//      window k. Flag at V_k > 12 (effective W-threshold 22.8 < 30: strictly
//      earlier than necessary -> sound).
//  (5) Range guards on eps/gam/sgain force the flag outside the proven range.
//
// Row-level quantities (per-window sum|x|, row max|x|) via one warp-shuffle
// reduction (warp w holds exactly x[128w..128w+127]).
__global__ __launch_bounds__(TPBC)
void coesn_cold(const float* __restrict__ x,      // (B, L)
                const float* __restrict__ x2h,    // (NHID)
                const float* __restrict__ bias,   // (NHID)
                const float* __restrict__ gamma_, // (NHID)
                const float* __restrict__ eps_,   // (NHID)
                const float* __restrict__ sgain,  // scalar
                float* __restrict__ out)          // (B, 2*NHID)
{
    __shared__ float sS[NWIN];   // per-window sum of |x|
    __shared__ float sM[NWIN];   // per-window max of |x|

    const int tid  = threadIdx.x;
    const int b    = blockIdx.x;
    const int warp = tid >> 5;
    const int lane = tid & 31;

    // ---- row-level |x| statistics: warp w == window w ----
    {
        const float4 v = ((const float4*)(x + (size_t)b * LSTEPS))[tid];
        float s = fabsf(v.x) + fabsf(v.y) + fabsf(v.z) + fabsf(v.w);
        float m = fmaxf(fmaxf(fabsf(v.x), fabsf(v.y)),
                        fmaxf(fabsf(v.z), fabsf(v.w)));
        #pragma unroll
        for (int off = 16; off >= 1; off >>= 1) {
            s += __shfl_down_sync(0xffffffffu, s, off);
            m  = fmaxf(m, __shfl_down_sync(0xffffffffu, m, off));
        }
        if (lane == 0) { sS[warp] = s; sM[warp] = m; }
    }
    __syncthreads();

    float Mrow = sM[0];
    #pragma unroll
    for (int k = 1; k < NWIN; ++k) Mrow = fmaxf(Mrow, sM[k]);

    const float dt     = 0.01f;
    const float LAM128 = 0.526f;   // >= lam^128 (larger = slower decay = sound)
    const float THRV   = 12.0f;    // effective W threshold 22.8 < 30

    // Parameter-range guard for the RF bound + sgain.
    bool flag;
    {
        const float sg = *sgain;
        float4 e = ((const float4*)eps_)[tid];
        float4 g = ((const float4*)gamma_)[tid];
        flag = !(sg >= 0.0f && sg <= 3.0001f)
            || !(e.x >= 1.0f && e.x <= 2.0001f) || !(e.y >= 1.0f && e.y <= 2.0001f)
            || !(e.z >= 1.0f && e.z <= 2.0001f) || !(e.w >= 1.0f && e.w <= 2.0001f)
            || !(g.x >= 2.0f && g.x <= 3.0001f) || !(g.y >= 2.0f && g.y <= 3.0001f)
            || !(g.z >= 2.0f && g.z <= 3.0001f) || !(g.w >= 2.0f && g.w <= 3.0001f);
    }

    // ---- per-neuron window recurrence (4 neurons/thread) ----
    {
        const float4 wraw = ((const float4*)x2h)[tid];
        const float4 braw = ((const float4*)bias)[tid];
        const float wq[4] = { fabsf(wraw.x), fabsf(wraw.y),
                              fabsf(wraw.z), fabsf(wraw.w) };
        const float bq[4] = { fmaxf(braw.x, 0.f), fmaxf(braw.y, 0.f),
                              fmaxf(braw.z, 0.f), fmaxf(braw.w, 0.f) };
        #pragma unroll
        for (int q = 0; q < NPTC; ++q) {
            const float Imax = dt * (bq[q] + wq[q] * Mrow);
            flag = flag || (Imax > 0.9f);
            const float V0 = 1.0f + Imax;            // start-of-window LIF bound
            const float Pb = dt * (float)WSTEP * bq[q];
            float Vk = 0.0f;
            #pragma unroll
            for (int k = 0; k < NWIN; ++k) {
                const float N = V0 + Pb + dt * wq[q] * sS[k];  // spike bound
                Vk = fmaf(Vk, LAM128, N);
                flag = flag || (Vk > THRV);
            }
        }
    }

    const bool ever = bar_red_or(flag);
    if (tid == 0) g_spiked[b] = ever ? 1 : 0;

    // Zero output (exact if no flag; fix kernel overwrites otherwise).
    float* o0 = out + (size_t)b * (2 * NHID) + tid * NPTC;
    const float4 z = make_float4(0.f, 0.f, 0.f, 0.f);
    ((float4*)o0)[0] = z;
    ((float4*)(o0 + NHID))[0] = z;
}

// ======================= FIX KERNEL (general coupled path) ================
// Full exact dynamics with recurrent h2h gather + ref/ft/fts, only for
// flagged rows (expected: none on this data; correctness net for any input).
__global__ __launch_bounds__(TPBF)
void coesn_fix(const float* __restrict__ x,
               const float* __restrict__ x2h,
               const float* __restrict__ h2h,
               const float* __restrict__ bias,
               const float* __restrict__ gamma_,
               const float* __restrict__ eps_,
               const float* __restrict__ sgain,
               float* __restrict__ out)
{
    const int b = blockIdx.x;
    if (g_spiked[b] == 0) return;      // uniform per CTA

    __shared__ float    xs[LSTEPS];
    __shared__ unsigned smask[TPBF];
    __shared__ float    sref[NHID], sft[NHID], sfts[NHID];

    const int tid = threadIdx.x;

    {
        const float4* xr = (const float4*)(x + (size_t)b * LSTEPS);
        ((float4*)xs)[tid]        = xr[tid];
        ((float4*)xs)[tid + TPBF] = xr[tid + TPBF];
    }

    const float dt = 0.01f;
    const float A  = 1.0f - dt / 20.0f;
    const float sg = *sgain;
    const float RD = expf(-dt / 0.25f);
    const float FD = expf(-dt / 10.0f);

    const float2 A2     = make_float2(A, A);
    const float2 DT2    = make_float2(dt, dt);
    const float2 NDTSG2 = make_float2(-dt * sg, -dt * sg);
    const float2 RD2    = make_float2(RD, RD);
    const float2 FD2    = make_float2(FD, FD);

    float2 W2[NPRF], B2[NPRF], EZ2[NPRF], GN2[NPRF];
    #pragma unroll
    for (int i = 0; i < 2; ++i) {
        float4 a;
        a = ((const float4*)x2h)[tid * 2 + i];
        W2[2*i]   = make_float2(dt*a.x, dt*a.y);
        W2[2*i+1] = make_float2(dt*a.z, dt*a.w);
        a = ((const float4*)bias)[tid * 2 + i];
        B2[2*i]   = make_float2(dt*a.x, dt*a.y);
        B2[2*i+1] = make_float2(dt*a.z, dt*a.w);
        a = ((const float4*)eps_)[tid * 2 + i];
        EZ2[2*i]   = make_float2(1.f-dt*a.x, 1.f-dt*a.y);
        EZ2[2*i+1] = make_float2(1.f-dt*a.z, 1.f-dt*a.w);
        a = ((const float4*)gamma_)[tid * 2 + i];
        GN2[2*i]   = make_float2(-dt*a.x, -dt*a.y);
        GN2[2*i+1] = make_float2(-dt*a.z, -dt*a.w);
    }

    float2 lif2[NPRF], hy2[NPRF], hz2[NPRF];
    #pragma unroll
    for (int p = 0; p < NPRF; ++p) {
        lif2[p] = make_float2(0.f, 0.f);
        hy2[p]  = make_float2(0.f, 0.f);
        hz2[p]  = make_float2(0.f, 0.f);
    }
    #pragma unroll
    for (int q = 0; q < NPTF; ++q) {
        const int n = tid * NPTF + q;
        sref[n] = 0.f; sft[n] = 0.f; sfts[n] = 0.f;
    }
    smask[tid] = 0u;
    __syncthreads();

    bool prev = false;
    #pragma unroll 1
    for (int t = 0; t < LSTEPS; ++t) {
        const float  xt  = xs[t];
        const float2 XT2 = make_float2(xt, xt);

        float2 acc[NPRF];
        #pragma unroll
        for (int p = 0; p < NPRF; ++p) acc[p] = make_float2(0.f, 0.f);

        if (prev) {
            for (int w = 0; w < TPBF; ++w) {
                unsigned mm_ = smask[w];
                while (mm_) {
                    const int k = __ffs(mm_) - 1; mm_ &= mm_ - 1;
                    const int j = w * NPTF + k;
                    const float4* hp =
                        (const float4*)(h2h + (size_t)j * NHID + tid * NPTF);
                    #pragma unroll
                    for (int i = 0; i < 2; ++i) {
                        float4 h = __ldg(hp + i);
                        acc[2*i].x   += h.x; acc[2*i].y   += h.y;
                        acc[2*i+1].x += h.z; acc[2*i+1].y += h.w;
                    }
                }
            }
        }

        bool any = false;
        unsigned msk = 0;
        #pragma unroll
        for (int p = 0; p < NPRF; ++p) {
            float2 I = ffma2(XT2, W2[p], B2[p]);
            I = ffma2(DT2, acc[p], I);
            lif2[p] = ffma2(lif2[p], A2, I);
            const bool l0 = lif2[p].x > 1.0f;
            const bool l1 = lif2[p].y > 1.0f;
            float2 ms = make_float2(l0 ? -1.0f : 0.0f, l1 ? -1.0f : 0.0f);
            lif2[p] = fadd2(lif2[p], ms);
            float2 k = fmul2(ms, NDTSG2);
            hz2[p] = ffma2(hz2[p], EZ2[p], ffma2(GN2[p], hy2[p], k));
            hy2[p] = ffma2(DT2, hz2[p], hy2[p]);

            const int n = tid * NPTF + 2 * p;
            float2 rf = make_float2(sref[n], sref[n+1]);
            const bool q0 = (hy2[p].x - 1.0f) > rf.x;
            const bool q1 = (hy2[p].y - 1.0f) > rf.y;
            float2 sn = make_float2(q0 ? 1.0f : 0.0f, q1 ? 1.0f : 0.0f);
            rf = ffma2(rf, RD2, sn);
            sref[n] = rf.x; sref[n+1] = rf.y;
            float2 f = make_float2(sft[n], sft[n+1]);
            f = ffma2(f, FD2, sn);
            sft[n] = f.x; sft[n+1] = f.y;
            sfts[n]   += f.x;
            sfts[n+1] += f.y;
            any = any || q0 || q1;
            msk |= (q0 ? 1u : 0u) << (2 * p);
            msk |= (q1 ? 1u : 0u) << (2 * p + 1);
        }
        smask[tid] = msk;
        prev = bar_red_or(any);
    }

    const float invL = 1.0f / (float)LSTEPS;
    float* o0 = out + (size_t)b * (2 * NHID) + tid * NPTF;
    float* o1 = o0 + NHID;
    #pragma unroll
    for (int i = 0; i < 2; ++i) {
        const int n = tid * NPTF + 4 * i;
        ((float4*)o0)[i] = make_float4(sfts[n]*invL, sfts[n+1]*invL,
                                       sfts[n+2]*invL, sfts[n+3]*invL);
        ((float4*)o1)[i] = make_float4(sft[n], sft[n+1], sft[n+2], sft[n+3]);
    }
}

extern "C" void kernel_launch(void* const* d_in, const int* in_sizes, int n_in,
                              void* d_out, int out_size)
{
    const float* x    = (const float*)d_in[0];
    const float* x2h  = (const float*)d_in[1];
    const float* h2h  = (const float*)d_in[2];
    const float* bias = (const float*)d_in[3];
    const float* gam  = (const float*)d_in[4];
    const float* eps  = (const float*)d_in[5];
    const float* sg   = (const float*)d_in[6];

    const int B = in_sizes[0] / LSTEPS;   // N_INP == 1
    coesn_cold<<<B, TPBC>>>(x, x2h, bias, gam, eps, sg, (float*)d_out);
    coesn_fix <<<B, TPBF>>>(x, x2h, h2h, bias, gam, eps, sg, (float*)d_out);
}